// round 5
// baseline (speedup 1.0000x reference)
#include <cuda_runtime.h>

#define B_ 64
#define N_ 2048
#define D_ 256
#define EPS_ 1e-5f

#define VEC_PER_B   (N_ * D_ / 4)        // 131072 float4 per batch
#define VEC_PER_ROW (D_ / 4)             // 64 float4 per row
#define SEGS        32
#define SEG_VEC     (VEC_PER_B / SEGS)   // 4096 float4 per segment
#define RED_THREADS 256

// Partial sums: [B][SEGS]. Written unconditionally every launch (zeros for
// fully-masked segments) -> deterministic, no reset pass, no atomics.
__device__ float g_psum[B_ * SEGS];
__device__ float g_psumsq[B_ * SEGS];
__device__ float g_mean[B_];
__device__ float g_inv[B_];

// ---------------------------------------------------------------- pass 1: partial sums per (segment, batch)
__global__ void __launch_bounds__(RED_THREADS)
sn_reduce_kernel(const float* __restrict__ x, const int* __restrict__ lengths) {
    int seg = blockIdx.x;                    // segment-major: consecutive blocks
    int b   = blockIdx.y;                    // walk contiguous addresses
    int len = __ldg(&lengths[b]);
    int valid_vec = len * VEC_PER_ROW;       // float4 count in valid region
    int base = seg * SEG_VEC;

    float s = 0.0f, sq = 0.0f;
    const float4* xv = reinterpret_cast<const float4*>(x) + (size_t)b * VEC_PER_B;

    if (base + SEG_VEC <= valid_vec) {
        // Fast path: segment fully valid -> unguarded, front-batched LDG.128s
#pragma unroll
        for (int k = 0; k < SEG_VEC / RED_THREADS; ++k) {
            float4 v = xv[base + threadIdx.x + k * RED_THREADS];
            s  += (v.x + v.y) + (v.z + v.w);
            sq += (v.x * v.x + v.y * v.y) + (v.z * v.z + v.w * v.w);
        }
    } else if (base < valid_vec) {
        // Boundary segment: guarded
#pragma unroll
        for (int k = 0; k < SEG_VEC / RED_THREADS; ++k) {
            int i = base + threadIdx.x + k * RED_THREADS;
            if (i < valid_vec) {
                float4 v = xv[i];
                s  += (v.x + v.y) + (v.z + v.w);
                sq += (v.x * v.x + v.y * v.y) + (v.z * v.z + v.w * v.w);
            }
        }
    }
    // else: fully masked segment -> contribute zeros

    // warp reduce
#pragma unroll
    for (int off = 16; off > 0; off >>= 1) {
        s  += __shfl_xor_sync(0xFFFFFFFFu, s,  off);
        sq += __shfl_xor_sync(0xFFFFFFFFu, sq, off);
    }

    __shared__ float sh_s[RED_THREADS / 32];
    __shared__ float sh_q[RED_THREADS / 32];
    int lane = threadIdx.x & 31;
    int wid  = threadIdx.x >> 5;
    if (lane == 0) { sh_s[wid] = s; sh_q[wid] = sq; }
    __syncthreads();

    if (wid == 0) {
        s  = (lane < RED_THREADS / 32) ? sh_s[lane] : 0.0f;
        sq = (lane < RED_THREADS / 32) ? sh_q[lane] : 0.0f;
#pragma unroll
        for (int off = 4; off > 0; off >>= 1) {
            s  += __shfl_xor_sync(0xFFFFFFFFu, s,  off);
            sq += __shfl_xor_sync(0xFFFFFFFFu, sq, off);
        }
        if (lane == 0) {
            g_psum[b * SEGS + seg]   = s;
            g_psumsq[b * SEGS + seg] = sq;
        }
    }
}

// ---------------------------------------------------------------- finalize: one warp per batch
__global__ void __launch_bounds__(64)
sn_finalize_kernel(const int* __restrict__ lengths) {
    int b    = blockIdx.x * 2 + (threadIdx.x >> 5);   // 2 warps/block, 32 blocks
    int lane = threadIdx.x & 31;
    if (b >= B_) return;

    float s  = g_psum[b * SEGS + lane];
    float sq = g_psumsq[b * SEGS + lane];
#pragma unroll
    for (int off = 16; off > 0; off >>= 1) {
        s  += __shfl_xor_sync(0xFFFFFFFFu, s,  off);
        sq += __shfl_xor_sync(0xFFFFFFFFu, sq, off);
    }
    if (lane == 0) {
        float denom = (float)lengths[b] * (float)D_;
        float mean  = s / denom;
        float var   = sq / denom - mean * mean;
        var = fmaxf(var, 0.0f);
        g_mean[b] = mean;
        g_inv[b]  = 1.0f / (sqrtf(var) + EPS_);
    }
}

// ---------------------------------------------------------------- pass 2: normalize + affine + mask
__global__ void __launch_bounds__(256)
sn_norm_kernel(const float4* __restrict__ x, const int* __restrict__ lengths,
               const float4* __restrict__ w, const float4* __restrict__ bias,
               float4* __restrict__ out) {
    int idx = blockIdx.x * blockDim.x + threadIdx.x;     // 0 .. B*N*D/4 - 1
    int b = idx >> 17;                                   // / VEC_PER_B (2^17)
    int r = idx & (VEC_PER_B - 1);
    int n = r >> 6;                                      // / VEC_PER_ROW (2^6)
    int len = __ldg(&lengths[b]);

    if (n >= len) {
        // Output is never re-read: streaming (evict-first) store keeps L2 for x.
        __stcs(&out[idx], make_float4(0.0f, 0.0f, 0.0f, 0.0f));
        return;
    }

    float4 v = x[idx];
    float m   = __ldg(&g_mean[b]);
    float inv = __ldg(&g_inv[b]);
    int dv = r & (VEC_PER_ROW - 1);
    float4 wv = w[dv];
    float4 bv = bias[dv];

    float4 o;
    o.x = fmaf((v.x - m) * inv, wv.x, bv.x);
    o.y = fmaf((v.y - m) * inv, wv.y, bv.y);
    o.z = fmaf((v.z - m) * inv, wv.z, bv.z);
    o.w = fmaf((v.w - m) * inv, wv.w, bv.w);
    __stcs(&out[idx], o);
}

// ---------------------------------------------------------------- launch
extern "C" void kernel_launch(void* const* d_in, const int* in_sizes, int n_in,
                              void* d_out, int out_size) {
    const float* x       = (const float*)d_in[0];
    const int*   lengths = (const int*)  d_in[1];
    const float* weights = (const float*)d_in[2];
    const float* biases  = (const float*)d_in[3];
    float*       out     = (float*)d_out;

    dim3 rgrid(SEGS, B_);   // 2048 blocks, segment-major -> contiguous walk
    sn_reduce_kernel<<<rgrid, RED_THREADS>>>(x, lengths);

    sn_finalize_kernel<<<32, 64>>>(lengths);

    int total_vec = B_ * VEC_PER_B;          // 8388608 vec4
    sn_norm_kernel<<<total_vec / 256, 256>>>(
        (const float4*)x, lengths,
        (const float4*)weights, (const float4*)biases,
        (float4*)out);
}